// round 5
// baseline (speedup 1.0000x reference)
#include <cuda_runtime.h>
#include <cstdint>
#include <math.h>

// ---------------- problem constants ----------------
#define Bc 1024   // batch
#define Tc 40     // timesteps
#define Ec 512    // embed dim
#define Hc 1024   // hidden
#define Lc 256    // latent out
#define Ac 2048   // feature dim
#define Vc 30000  // vocab
#define Nw 4096   // 4*H

// ---------------- device scratch (no allocation) ----------------
__device__ float g_Wcat [2 * Hc * Ac];   // [Wih0 ; Wic0] weight-normed, tf32-rounded
__device__ float g_bcat [2 * Hc];        // [b_ih0 ; b_ic0]
__device__ float g_Wocat[2 * Lc * Hc];   // [Wmu ; Ws2] weight-normed, tf32-rounded
__device__ float g_bocat[2 * Lc];        // [b_mu ; b_s2]
__device__ float g_Wp   [Nw * (Hc + Ec)];// permuted [4j+gate][W_hh | W_ih], tf32-rounded
__device__ float g_pb   [Nw];            // permuted bias b_ih+b_hh
__device__ float g_hbuf [2][Bc * Hc];    // double-buffered hidden (tf32-rounded)
__device__ float g_c    [Bc * Hc];       // cell state (full fp32)
__device__ float g_hl   [Bc * Hc];       // h at last valid step (tf32-rounded)
__device__ float g_embR [Vc * Ec];       // tf32-rounded embedding
__device__ float g_ftR  [Bc * Ac];       // tf32-rounded feat_vec
__device__ float g_X    [(size_t)Tc * Bc * Nw]; // precomputed input gates (671 MB)

// ---------------- helpers ----------------
__device__ __forceinline__ float to_tf32(float x) {
    float r;
    asm("cvt.rna.tf32.f32 %0, %1;" : "=f"(r) : "f"(x));
    return r;
}
__device__ __forceinline__ uint32_t smem_u32(const void* p) {
    uint32_t a;
    asm("{ .reg .u64 t; cvta.to.shared.u64 t, %1; cvt.u32.u64 %0, t; }" : "=r"(a) : "l"(p));
    return a;
}
#define CP_ASYNC16(dst, src) \
    asm volatile("cp.async.cg.shared.global [%0], [%1], 16;" :: "r"(dst), "l"(src))
#define CP_COMMIT() asm volatile("cp.async.commit_group;" ::: "memory")
#define CP_WAIT1()  asm volatile("cp.async.wait_group 1;" ::: "memory")

__device__ __forceinline__ void mma_tf32(float* d, const uint32_t* a, const uint32_t* b) {
    asm volatile(
        "mma.sync.aligned.m16n8k8.row.col.f32.tf32.tf32.f32 "
        "{%0,%1,%2,%3}, {%4,%5,%6,%7}, {%8,%9}, {%0,%1,%2,%3};"
        : "+f"(d[0]), "+f"(d[1]), "+f"(d[2]), "+f"(d[3])
        : "r"(a[0]), "r"(a[1]), "r"(a[2]), "r"(a[3]), "r"(b[0]), "r"(b[1]));
}

// ---------------- prep kernels ----------------
__global__ void wn_kernel(const float* __restrict__ v, const float* __restrict__ g,
                          float* __restrict__ W, int cols) {
    int r = blockIdx.x;
    const float* vr = v + (size_t)r * cols;
    float s = 0.f;
    for (int c = threadIdx.x; c < cols; c += blockDim.x) { float x = vr[c]; s += x * x; }
    __shared__ float sh[32];
    for (int o = 16; o > 0; o >>= 1) s += __shfl_down_sync(0xffffffffu, s, o);
    if ((threadIdx.x & 31) == 0) sh[threadIdx.x >> 5] = s;
    __syncthreads();
    if (threadIdx.x < 32) {
        float t = (threadIdx.x < (blockDim.x >> 5)) ? sh[threadIdx.x] : 0.f;
        for (int o = 16; o > 0; o >>= 1) t += __shfl_down_sync(0xffffffffu, t, o);
        if (threadIdx.x == 0) sh[0] = t;
    }
    __syncthreads();
    float scale = g[r] / sqrtf(sh[0]);
    float* Wr = W + (size_t)r * cols;
    for (int c = threadIdx.x; c < cols; c += blockDim.x) Wr[c] = to_tf32(vr[c] * scale);
}

__global__ void permute_kernel(const float* __restrict__ Whh, const float* __restrict__ Wih,
                               const float* __restrict__ bih, const float* __restrict__ bhh,
                               float* __restrict__ Wp, float* __restrict__ pb) {
    int n = blockIdx.x;
    int gt = n >> 10, j = n & 1023;
    int np = (j << 2) | gt;
    float* dst = Wp + (size_t)np * (Hc + Ec);
    const float* s1 = Whh + (size_t)n * Hc;
    const float* s2 = Wih + (size_t)n * Ec;
    for (int k = threadIdx.x; k < Hc; k += blockDim.x) dst[k] = to_tf32(s1[k]);
    for (int k = threadIdx.x; k < Ec; k += blockDim.x) dst[Hc + k] = to_tf32(s2[k]);
    if (threadIdx.x == 0) pb[np] = bih[n] + bhh[n];
}

__global__ void round_copy(const float* __restrict__ src, float* __restrict__ dst, int n) {
    int i = blockIdx.x * blockDim.x + threadIdx.x;
    if (i < n) dst[i] = to_tf32(src[i]);
}

__global__ void pack2(const float* __restrict__ a, const float* __restrict__ b,
                      float* __restrict__ dst, int n) {
    int i = blockIdx.x * blockDim.x + threadIdx.x;
    if (i < n) dst[i] = a[i];
    else if (i < 2 * n) dst[i] = b[i - n];
}

// ---------------- mma.sync tf32 GEMM ----------------
// CTA tile 128(M) x 128(N). 8 warps: 2(M) x 4(N), warp tile 64 x 32.
// K in chunks of 32, 3-stage cp.async pipeline, one __syncthreads per chunk.
// 2 CTAs/SM co-residency (109 KB smem, <=128 regs).
// MODE 0: C = A*W^T + bias, split at column ncut -> (C1,ldc1,round1)/(C2,ldc2,round2)
// MODE 1: recurrent step: gates = acc + X[t]; fused LSTM cell -> c, h, h_last
// GATHER 1: A rows gathered from embR via cap with m=(t*1024+b) mapping (X precompute)
static constexpr int NREG  = 4;
static constexpr int NT    = 128;
static constexpr int A_OFF = 1024;
static constexpr int TILE_ST = 128 * 36 * 4;             // 18432 (A or B stage)
static constexpr int B_OFF = A_OFF + 3 * TILE_ST;
static constexpr int SMEM_BYTES = B_OFF + 3 * TILE_ST;   // 111616
static constexpr int GSTR  = 132;                        // gate staging row stride

template <int MODE, int GATHER>
__global__ __launch_bounds__(256, 2)
void tc_gemm(const float* __restrict__ A1, int lda1, int kc1,
             const float* __restrict__ A2, int lda2, int kc2,
             const int* __restrict__ cap,
             const float* __restrict__ Bw, int ldb,
             const float* __restrict__ bias,
             float* __restrict__ C1, int ldc1, int round1,
             float* __restrict__ C2, int ldc2, int round2, int ncut,
             const float* __restrict__ X, int t,
             const int* __restrict__ cap_len,
             float* __restrict__ cst, float* __restrict__ hst,
             float* __restrict__ hlast)
{
    extern __shared__ __align__(1024) char smem[];
    uint32_t sb = smem_u32(smem);
    int tid = threadIdx.x, wid = tid >> 5, lid = tid & 31;
    int g = lid >> 2, tig = lid & 3;
    int warpM = (wid & 1) * 64, warpN = (wid >> 1) * 32;
    int bm = blockIdx.y * 128, bn = blockIdx.x * NT;
    const int NC = kc1 + kc2;
    int* stok = (int*)smem;

    if (GATHER && tid < 128)
        stok[tid] = cap[(size_t)((bm & 1023) + tid) * Tc + (bm >> 10)];
    __syncthreads();

    float acc[4][NREG][4];
#pragma unroll
    for (int i = 0; i < 4; i++)
#pragma unroll
        for (int j = 0; j < NREG; j++)
#pragma unroll
            for (int q = 0; q < 4; q++) acc[i][j][q] = 0.f;

    auto load_chunk = [&](int c, int s) {
        uint32_t aB = sb + A_OFF + s * TILE_ST;
        uint32_t bB = sb + B_OFF + s * TILE_ST;
        bool seg1 = (c < kc1);
        int kbase = seg1 ? c * 32 : (c - kc1) * 32;
#pragma unroll
        for (int i = 0; i < 4; i++) {               // A tile: 128 rows x 32 floats
            int seg = tid + i * 256;
            int m = seg >> 3, ch = seg & 7;
            const float* src;
            if (GATHER) src = A2 + (size_t)stok[m] * lda2 + kbase + ch * 4;
            else        src = A1 + (size_t)(bm + m) * lda1 + kbase + ch * 4;
            CP_ASYNC16(aB + m * 144 + ch * 16, src);
        }
#pragma unroll
        for (int i = 0; i < 4; i++) {               // B tile: 128 rows x 32 floats
            int seg = tid + i * 256;
            int n = seg >> 3, ch = seg & 7;
            CP_ASYNC16(bB + n * 144 + ch * 16,
                       Bw + (size_t)(bn + n) * ldb + c * 32 + ch * 4);
        }
    };

    // prologue: fill 2 of 3 stages
    load_chunk(0, 0); CP_COMMIT();
    load_chunk(1, 1); CP_COMMIT();

    int s = 0;
    for (int c = 0; c < NC; c++) {
        CP_WAIT1();                 // chunk c resident
        __syncthreads();            // all reads of slot (c+2)%3 done (iter c-1)
        if (c + 2 < NC) load_chunk(c + 2, (c + 2) % 3);
        CP_COMMIT();
        const uint32_t* aU = (const uint32_t*)(smem + A_OFF + s * TILE_ST);
        const uint32_t* bU = (const uint32_t*)(smem + B_OFF + s * TILE_ST);
#pragma unroll
        for (int kk = 0; kk < 4; kk++) {
            uint32_t afr[4][4], bfr[NREG][2];
            int kb = kk * 8 + tig;
#pragma unroll
            for (int rb = 0; rb < 4; rb++) {
                int ar = warpM + rb * 16 + g;
                afr[rb][0] = aU[ar * 36 + kb];
                afr[rb][1] = aU[(ar + 8) * 36 + kb];
                afr[rb][2] = aU[ar * 36 + kb + 4];
                afr[rb][3] = aU[(ar + 8) * 36 + kb + 4];
            }
#pragma unroll
            for (int nb = 0; nb < NREG; nb++) {
                int br = warpN + nb * 8 + g;
                bfr[nb][0] = bU[br * 36 + kb];
                bfr[nb][1] = bU[br * 36 + kb + 4];
            }
#pragma unroll
            for (int rb = 0; rb < 4; rb++)
#pragma unroll
                for (int nb = 0; nb < NREG; nb++)
                    mma_tf32(acc[rb][nb], afr[rb], bfr[nb]);
        }
        s++; if (s == 3) s = 0;
    }

    // ---------------- epilogue ----------------
    if (MODE == 0) {
        float* Cd; int cb, ldc, rnd;
        if (bn < ncut) { Cd = C1; cb = bn;        ldc = ldc1; rnd = round1; }
        else           { Cd = C2; cb = bn - ncut; ldc = ldc2; rnd = round2; }
#pragma unroll
        for (int rb = 0; rb < 4; rb++) {
#pragma unroll
            for (int nb = 0; nb < NREG; nb++) {
                int coll = warpN + nb * 8 + 2 * tig;
                int col = cb + coll;
                int r0 = bm + warpM + rb * 16 + g;
                float b0 = bias[bn + coll], b1 = bias[bn + coll + 1];
                float v0 = acc[rb][nb][0] + b0, v1 = acc[rb][nb][1] + b1;
                float v2 = acc[rb][nb][2] + b0, v3 = acc[rb][nb][3] + b1;
                if (rnd) { v0 = to_tf32(v0); v1 = to_tf32(v1); v2 = to_tf32(v2); v3 = to_tf32(v3); }
                *(float2*)(Cd + (size_t)r0 * ldc + col)       = make_float2(v0, v1);
                *(float2*)(Cd + (size_t)(r0 + 8) * ldc + col) = make_float2(v2, v3);
            }
        }
    } else {
        __syncthreads();   // protect smem reuse for gate staging
        float* gsm = (float*)(smem + A_OFF);
#pragma unroll
        for (int rb = 0; rb < 4; rb++) {
#pragma unroll
            for (int nb = 0; nb < NREG; nb++) {
                int col = warpN + nb * 8 + 2 * tig;
                int r0 = warpM + rb * 16 + g;
                *(float2*)(gsm + r0 * GSTR + col)       = make_float2(acc[rb][nb][0], acc[rb][nb][1]);
                *(float2*)(gsm + (r0 + 8) * GSTR + col) = make_float2(acc[rb][nb][2], acc[rb][nb][3]);
            }
        }
        __syncthreads();
        for (int idx = tid; idx < 128 * 32; idx += 256) {
            int row = idx >> 5, jl = idx & 31;
            int gm = bm + row;
            int jg = (bn >> 2) + jl;
            float4 gv = *(const float4*)(gsm + row * GSTR + jl * 4);
            float4 xv = *(const float4*)(X + ((size_t)t * Bc + gm) * Nw + bn + jl * 4);
            float gi = gv.x + xv.x;
            float gf = gv.y + xv.y;
            float gg = gv.z + xv.z;
            float go = gv.w + xv.w;
            float si = 1.f / (1.f + expf(-gi));
            float sf = 1.f / (1.f + expf(-gf));
            float so = 1.f / (1.f + expf(-go));
            size_t off = (size_t)gm * Hc + jg;
            float cn = sf * cst[off] + si * tanhf(gg);
            float hn = to_tf32(so * tanhf(cn));
            cst[off] = cn;
            hst[off] = hn;
            if (cap_len[gm] - 1 == t) hlast[off] = hn;
        }
    }
}

// ---------------- launch ----------------
extern "C" void kernel_launch(void* const* d_in, const int* in_sizes, int n_in,
                              void* d_out, int out_size) {
    const int*   cap     = (const int*)  d_in[0];
    const int*   cap_len = (const int*)  d_in[1];
    const float* feat    = (const float*)d_in[2];
    const float* embed   = (const float*)d_in[3];
    const float* W_ih    = (const float*)d_in[4];
    const float* W_hh    = (const float*)d_in[5];
    const float* b_ih    = (const float*)d_in[6];
    const float* b_hh    = (const float*)d_in[7];
    const float* v_ih0   = (const float*)d_in[8];
    const float* g_ih0   = (const float*)d_in[9];
    const float* b_ih0   = (const float*)d_in[10];
    const float* v_ic0   = (const float*)d_in[11];
    const float* g_ic0   = (const float*)d_in[12];
    const float* b_ic0   = (const float*)d_in[13];
    const float* v_mu    = (const float*)d_in[14];
    const float* g_mu    = (const float*)d_in[15];
    const float* b_mu    = (const float*)d_in[16];
    const float* v_s2    = (const float*)d_in[17];
    const float* g_s2    = (const float*)d_in[18];
    const float* b_s2    = (const float*)d_in[19];
    float* out = (float*)d_out;

    float *Wcat, *bcat, *Wocat, *bocat, *Wp, *pb, *hbuf, *c, *hl, *embR, *ftR, *X;
    cudaGetSymbolAddress((void**)&Wcat,  g_Wcat);
    cudaGetSymbolAddress((void**)&bcat,  g_bcat);
    cudaGetSymbolAddress((void**)&Wocat, g_Wocat);
    cudaGetSymbolAddress((void**)&bocat, g_bocat);
    cudaGetSymbolAddress((void**)&Wp,    g_Wp);
    cudaGetSymbolAddress((void**)&pb,    g_pb);
    cudaGetSymbolAddress((void**)&hbuf,  g_hbuf);
    cudaGetSymbolAddress((void**)&c,     g_c);
    cudaGetSymbolAddress((void**)&hl,    g_hl);
    cudaGetSymbolAddress((void**)&embR,  g_embR);
    cudaGetSymbolAddress((void**)&ftR,   g_ftR);
    cudaGetSymbolAddress((void**)&X,     g_X);

    cudaFuncSetAttribute(tc_gemm<0,0>, cudaFuncAttributeMaxDynamicSharedMemorySize, SMEM_BYTES);
    cudaFuncSetAttribute(tc_gemm<0,1>, cudaFuncAttributeMaxDynamicSharedMemorySize, SMEM_BYTES);
    cudaFuncSetAttribute(tc_gemm<1,0>, cudaFuncAttributeMaxDynamicSharedMemorySize, SMEM_BYTES);

    // prep: weight norm (tf32), permute, round activations
    wn_kernel<<<Hc, 256>>>(v_ih0, g_ih0, Wcat,            Ac);
    wn_kernel<<<Hc, 256>>>(v_ic0, g_ic0, Wcat + Hc * Ac,  Ac);
    wn_kernel<<<Lc, 256>>>(v_mu,  g_mu,  Wocat,           Hc);
    wn_kernel<<<Lc, 256>>>(v_s2,  g_s2,  Wocat + Lc * Hc, Hc);
    pack2<<<(2 * Hc + 255) / 256, 256>>>(b_ih0, b_ic0, bcat, Hc);
    pack2<<<(2 * Lc + 255) / 256, 256>>>(b_mu,  b_s2,  bocat, Lc);
    permute_kernel<<<Nw, 256>>>(W_hh, W_ih, b_ih, b_hh, Wp, pb);
    round_copy<<<(Vc * Ec + 255) / 256, 256>>>(embed, embR, Vc * Ec);
    round_copy<<<(Bc * Ac + 255) / 256, 256>>>(feat, ftR, Bc * Ac);

    // X precompute: X[t*B+b, :] = emb(cap[b,t]) @ W_ih^T + (b_ih+b_hh), permuted cols
    {
        dim3 grid(Nw / NT, (Tc * Bc) / 128);   // (32, 320) = 10240 CTAs
        tc_gemm<0,1><<<grid, 256, SMEM_BYTES>>>(nullptr, 0, 0, embR, Ec, Ec / 32, cap,
                                                Wp + Hc, Hc + Ec, pb,
                                                X, Nw, 0, nullptr, 0, 0, 1 << 30,
                                                nullptr, 0, nullptr, nullptr, nullptr, nullptr);
    }

    // init: h0 (tf32-rounded) and c0 (fp32), fused N=2048
    {
        dim3 grid(2 * Hc / NT, Bc / 128);      // (16, 8)
        tc_gemm<0,0><<<grid, 256, SMEM_BYTES>>>(ftR, Ac, Ac / 32, nullptr, 0, 0, nullptr,
                                                Wcat, Ac, bcat,
                                                hbuf, Hc, 1, c, Hc, 0, Hc,
                                                nullptr, 0, nullptr, nullptr, nullptr, nullptr);
    }

    // recurrence: h @ W_hh^T (K=1024) + X[t], fused LSTM cell
    {
        dim3 grid(Nw / NT, Bc / 128);          // (32, 8) = 256 CTAs, 2/SM
        for (int t = 0; t < Tc; t++) {
            float* hin  = hbuf + (size_t)(t & 1) * Bc * Hc;
            float* hout = hbuf + (size_t)((t + 1) & 1) * Bc * Hc;
            tc_gemm<1,0><<<grid, 256, SMEM_BYTES>>>(hin, Hc, Hc / 32, nullptr, 0, 0, nullptr,
                                                    Wp, Hc + Ec, nullptr,
                                                    nullptr, 0, 0, nullptr, 0, 0, 0,
                                                    X, t, cap_len, c, hout, hl);
        }
    }

    // outputs: mu and sigma2 fused, N=512
    {
        dim3 grid(2 * Lc / NT, Bc / 128);      // (4, 8)
        tc_gemm<0,0><<<grid, 256, SMEM_BYTES>>>(hl, Hc, Hc / 32, nullptr, 0, 0, nullptr,
                                                Wocat, Hc, bocat,
                                                out, Lc, 0, out + Bc * Lc, Lc, 0, Lc,
                                                nullptr, 0, nullptr, nullptr, nullptr, nullptr);
    }
}

// round 6
// speedup vs baseline: 1.6393x; 1.6393x over previous
#include <cuda_runtime.h>
#include <cuda_fp16.h>
#include <cstdint>
#include <math.h>

// ---------------- problem constants ----------------
#define Bc 1024   // batch
#define Tc 40     // timesteps
#define Ec 512    // embed dim
#define Hc 1024   // hidden
#define Lc 256    // latent out
#define Ac 2048   // feature dim
#define Vc 30000  // vocab
#define Nw 4096   // 4*H

// ---------------- device scratch (no allocation) ----------------
__device__ __half g_Wcat [2 * Hc * Ac];   // [Wih0 ; Wic0] weight-normed fp16
__device__ float  g_bcat [2 * Hc];        // [b_ih0 ; b_ic0]
__device__ __half g_Wocat[2 * Lc * Hc];   // [Wmu ; Ws2] weight-normed fp16
__device__ float  g_bocat[2 * Lc];        // [b_mu ; b_s2]
__device__ __half g_Wp   [Nw * (Hc + Ec)];// permuted [4j+gate][W_hh | W_ih] fp16
__device__ float  g_pb   [Nw];            // permuted bias b_ih+b_hh
__device__ __half g_hbuf [2][Bc * Hc];    // double-buffered hidden (fp16)
__device__ float  g_c    [Bc * Hc];       // cell state (fp32)
__device__ __half g_hl   [Bc * Hc];       // h at last valid step (fp16)
__device__ __half g_embH [Vc * Ec];       // fp16 embedding
__device__ __half g_ftH  [Bc * Ac];       // fp16 feat_vec

// ---------------- helpers ----------------
__device__ __forceinline__ uint32_t smem_u32(const void* p) {
    uint32_t a;
    asm("{ .reg .u64 t; cvta.to.shared.u64 t, %1; cvt.u32.u64 %0, t; }" : "=r"(a) : "l"(p));
    return a;
}
#define CP_ASYNC16(dst, src) \
    asm volatile("cp.async.cg.shared.global [%0], [%1], 16;" :: "r"(dst), "l"(src))
#define CP_COMMIT() asm volatile("cp.async.commit_group;" ::: "memory")
#define CP_WAIT2()  asm volatile("cp.async.wait_group 2;" ::: "memory")

__device__ __forceinline__ void mma_f16(float* d, const uint32_t* a, const uint32_t* b) {
    asm volatile(
        "mma.sync.aligned.m16n8k16.row.col.f32.f16.f16.f32 "
        "{%0,%1,%2,%3}, {%4,%5,%6,%7}, {%8,%9}, {%0,%1,%2,%3};"
        : "+f"(d[0]), "+f"(d[1]), "+f"(d[2]), "+f"(d[3])
        : "r"(a[0]), "r"(a[1]), "r"(a[2]), "r"(a[3]), "r"(b[0]), "r"(b[1]));
}

// ---------------- prep kernels ----------------
__global__ void wn_kernel(const float* __restrict__ v, const float* __restrict__ g,
                          __half* __restrict__ W, int cols) {
    int r = blockIdx.x;
    const float* vr = v + (size_t)r * cols;
    float s = 0.f;
    for (int c = threadIdx.x; c < cols; c += blockDim.x) { float x = vr[c]; s += x * x; }
    __shared__ float sh[32];
    for (int o = 16; o > 0; o >>= 1) s += __shfl_down_sync(0xffffffffu, s, o);
    if ((threadIdx.x & 31) == 0) sh[threadIdx.x >> 5] = s;
    __syncthreads();
    if (threadIdx.x < 32) {
        float t = (threadIdx.x < (blockDim.x >> 5)) ? sh[threadIdx.x] : 0.f;
        for (int o = 16; o > 0; o >>= 1) t += __shfl_down_sync(0xffffffffu, t, o);
        if (threadIdx.x == 0) sh[0] = t;
    }
    __syncthreads();
    float scale = g[r] / sqrtf(sh[0]);
    __half* Wr = W + (size_t)r * cols;
    for (int c = threadIdx.x; c < cols; c += blockDim.x) Wr[c] = __float2half_rn(vr[c] * scale);
}

__global__ void permute_kernel(const float* __restrict__ Whh, const float* __restrict__ Wih,
                               const float* __restrict__ bih, const float* __restrict__ bhh,
                               __half* __restrict__ Wp, float* __restrict__ pb) {
    int n = blockIdx.x;
    int gt = n >> 10, j = n & 1023;
    int np = (j << 2) | gt;
    __half* dst = Wp + (size_t)np * (Hc + Ec);
    const float* s1 = Whh + (size_t)n * Hc;
    const float* s2 = Wih + (size_t)n * Ec;
    for (int k = threadIdx.x; k < Hc; k += blockDim.x) dst[k] = __float2half_rn(s1[k]);
    for (int k = threadIdx.x; k < Ec; k += blockDim.x) dst[Hc + k] = __float2half_rn(s2[k]);
    if (threadIdx.x == 0) pb[np] = bih[n] + bhh[n];
}

__global__ void half_copy(const float* __restrict__ src, __half* __restrict__ dst, int n) {
    int i = blockIdx.x * blockDim.x + threadIdx.x;
    if (i < n) dst[i] = __float2half_rn(src[i]);
}

__global__ void pack2(const float* __restrict__ a, const float* __restrict__ b,
                      float* __restrict__ dst, int n) {
    int i = blockIdx.x * blockDim.x + threadIdx.x;
    if (i < n) dst[i] = a[i];
    else if (i < 2 * n) dst[i] = b[i - n];
}

// ---------------- fp16 mma.sync GEMM ----------------
// CTA tile 128(M) x 128(N). 8 warps: 2(M) x 4(N), warp tile 64 x 32.
// K chunks of 32, 4-stage cp.async pipeline, one __syncthreads per chunk, 2 CTAs/SM.
// SMEM rows padded to 80 B (40 fp16) -> conflict-free fragment loads.
// MODE 0: C = A*W^T + bias, split at ncut -> (C1,ldc1,half1)/(C2,ldc2,half2)
// MODE 1: fused LSTM cell epilogue (N permuted 4j+gate) -> c(fp32), h(fp16), h_last(fp16)
static constexpr int A_OFF = 1024;
static constexpr int ST    = 128 * 80;                    // 10240 B per stage (A or B)
static constexpr int B_OFF = A_OFF + 4 * ST;
static constexpr int SMEM_BYTES = B_OFF + 4 * ST;         // 82944
static constexpr int GSTR  = 132;                         // fp32 gate staging row stride

template <int MODE>
__global__ __launch_bounds__(256, 2)
void hgemm(const __half* __restrict__ A1, int lda1, int kc1,
           const __half* __restrict__ A2, int lda2, int kc2,
           const int* __restrict__ cap, int t,
           const __half* __restrict__ Bw, int ldb,
           const float* __restrict__ bias,
           float* __restrict__ C1, int ldc1, int half1,
           float* __restrict__ C2, int ldc2, int half2, int ncut,
           const int* __restrict__ cap_len,
           float* __restrict__ cst, __half* __restrict__ hst,
           __half* __restrict__ hlast)
{
    extern __shared__ __align__(1024) char smem[];
    uint32_t sb = smem_u32(smem);
    int tid = threadIdx.x, wid = tid >> 5, lid = tid & 31;
    int g = lid >> 2, tig = lid & 3;
    int warpM = (wid & 1) * 64, warpN = (wid >> 1) * 32;
    int bm = blockIdx.y * 128, bn = blockIdx.x * 128;
    const int NC = kc1 + kc2;
    int* stok = (int*)smem;

    if (kc2 > 0 && tid < 128) stok[tid] = cap[(size_t)(bm + tid) * Tc + t];
    __syncthreads();

    float acc[4][4][4];
#pragma unroll
    for (int i = 0; i < 4; i++)
#pragma unroll
        for (int j = 0; j < 4; j++)
#pragma unroll
            for (int q = 0; q < 4; q++) acc[i][j][q] = 0.f;

    auto load_chunk = [&](int c, int s) {
        uint32_t aB = sb + A_OFF + s * ST;
        uint32_t bB = sb + B_OFF + s * ST;
        bool seg1 = (c < kc1);
        int kbase = seg1 ? c * 32 : (c - kc1) * 32;
#pragma unroll
        for (int i = 0; i < 2; i++) {               // A: 128 rows x 64 B (4 segs/row)
            int seg = tid + i * 256;
            int m = seg >> 2, sg = seg & 3;
            const __half* src = seg1
                ? (A1 + (size_t)(bm + m) * lda1 + kbase + sg * 8)
                : (A2 + (size_t)stok[m] * lda2 + kbase + sg * 8);
            CP_ASYNC16(aB + m * 80 + sg * 16, src);
        }
#pragma unroll
        for (int i = 0; i < 2; i++) {               // B: 128 rows x 64 B
            int seg = tid + i * 256;
            int n = seg >> 2, sg = seg & 3;
            CP_ASYNC16(bB + n * 80 + sg * 16,
                       Bw + (size_t)(bn + n) * ldb + c * 32 + sg * 8);
        }
    };

    // prologue: fill 3 of 4 stages
    for (int p = 0; p < 3; p++) { load_chunk(p, p); CP_COMMIT(); }

    for (int c = 0; c < NC; c++) {
        int s = c & 3;
        CP_WAIT2();                 // chunk c resident
        __syncthreads();            // all reads of slot (c+3)&3 done (iter c-1)
        if (c + 3 < NC) load_chunk(c + 3, (c + 3) & 3);
        CP_COMMIT();
        const uint32_t* aU = (const uint32_t*)(smem + A_OFF + s * ST);
        const uint32_t* bU = (const uint32_t*)(smem + B_OFF + s * ST);
#pragma unroll
        for (int k16 = 0; k16 < 2; k16++) {
            uint32_t afr[4][4], bfr[4][2];
            int kb = k16 * 8 + tig;
#pragma unroll
            for (int rb = 0; rb < 4; rb++) {
                int ar = warpM + rb * 16 + g;
                afr[rb][0] = aU[ar * 20 + kb];
                afr[rb][1] = aU[(ar + 8) * 20 + kb];
                afr[rb][2] = aU[ar * 20 + kb + 4];
                afr[rb][3] = aU[(ar + 8) * 20 + kb + 4];
            }
#pragma unroll
            for (int nb = 0; nb < 4; nb++) {
                int br = warpN + nb * 8 + g;
                bfr[nb][0] = bU[br * 20 + kb];
                bfr[nb][1] = bU[br * 20 + kb + 4];
            }
#pragma unroll
            for (int rb = 0; rb < 4; rb++)
#pragma unroll
                for (int nb = 0; nb < 4; nb++)
                    mma_f16(acc[rb][nb], afr[rb], bfr[nb]);
        }
    }

    // ---------------- epilogue ----------------
    if (MODE == 0) {
        float* Cd; int cb, ldc, hf;
        if (bn < ncut) { Cd = C1; cb = bn;        ldc = ldc1; hf = half1; }
        else           { Cd = C2; cb = bn - ncut; ldc = ldc2; hf = half2; }
#pragma unroll
        for (int rb = 0; rb < 4; rb++) {
#pragma unroll
            for (int nb = 0; nb < 4; nb++) {
                int coll = warpN + nb * 8 + 2 * tig;
                int col = cb + coll;
                int r0 = bm + warpM + rb * 16 + g;
                float b0 = bias[bn + coll], b1 = bias[bn + coll + 1];
                float v0 = acc[rb][nb][0] + b0, v1 = acc[rb][nb][1] + b1;
                float v2 = acc[rb][nb][2] + b0, v3 = acc[rb][nb][3] + b1;
                if (hf) {
                    __half* Ch = (__half*)Cd;
                    __half2 p0 = __floats2half2_rn(v0, v1);
                    __half2 p1 = __floats2half2_rn(v2, v3);
                    *(__half2*)(Ch + (size_t)r0 * ldc + col)       = p0;
                    *(__half2*)(Ch + (size_t)(r0 + 8) * ldc + col) = p1;
                } else {
                    *(float2*)(Cd + (size_t)r0 * ldc + col)       = make_float2(v0, v1);
                    *(float2*)(Cd + (size_t)(r0 + 8) * ldc + col) = make_float2(v2, v3);
                }
            }
        }
    } else {
        __syncthreads();   // smem reuse for gate staging
        float* gsm = (float*)(smem + A_OFF);
#pragma unroll
        for (int rb = 0; rb < 4; rb++) {
#pragma unroll
            for (int nb = 0; nb < 4; nb++) {
                int col = warpN + nb * 8 + 2 * tig;
                int r0 = warpM + rb * 16 + g;
                *(float2*)(gsm + r0 * GSTR + col)       = make_float2(acc[rb][nb][0], acc[rb][nb][1]);
                *(float2*)(gsm + (r0 + 8) * GSTR + col) = make_float2(acc[rb][nb][2], acc[rb][nb][3]);
            }
        }
        __syncthreads();
        for (int idx = tid; idx < 128 * 32; idx += 256) {
            int row = idx >> 5, jl = idx & 31;
            int gm = bm + row;
            int jg = (bn >> 2) + jl;
            float4 gv = *(const float4*)(gsm + row * GSTR + jl * 4);
            int nb4 = bn + jl * 4;
            float gi = gv.x + bias[nb4 + 0];
            float gf = gv.y + bias[nb4 + 1];
            float gg = gv.z + bias[nb4 + 2];
            float go = gv.w + bias[nb4 + 3];
            float si = 1.f / (1.f + expf(-gi));
            float sf = 1.f / (1.f + expf(-gf));
            float so = 1.f / (1.f + expf(-go));
            size_t off = (size_t)gm * Hc + jg;
            float cn = sf * cst[off] + si * tanhf(gg);
            __half hn = __float2half_rn(so * tanhf(cn));
            cst[off] = cn;
            hst[off] = hn;
            if (cap_len[gm] - 1 == t) hlast[off] = hn;
        }
    }
}

// ---------------- launch ----------------
extern "C" void kernel_launch(void* const* d_in, const int* in_sizes, int n_in,
                              void* d_out, int out_size) {
    const int*   cap     = (const int*)  d_in[0];
    const int*   cap_len = (const int*)  d_in[1];
    const float* feat    = (const float*)d_in[2];
    const float* embed   = (const float*)d_in[3];
    const float* W_ih    = (const float*)d_in[4];
    const float* W_hh    = (const float*)d_in[5];
    const float* b_ih    = (const float*)d_in[6];
    const float* b_hh    = (const float*)d_in[7];
    const float* v_ih0   = (const float*)d_in[8];
    const float* g_ih0   = (const float*)d_in[9];
    const float* b_ih0   = (const float*)d_in[10];
    const float* v_ic0   = (const float*)d_in[11];
    const float* g_ic0   = (const float*)d_in[12];
    const float* b_ic0   = (const float*)d_in[13];
    const float* v_mu    = (const float*)d_in[14];
    const float* g_mu    = (const float*)d_in[15];
    const float* b_mu    = (const float*)d_in[16];
    const float* v_s2    = (const float*)d_in[17];
    const float* g_s2    = (const float*)d_in[18];
    const float* b_s2    = (const float*)d_in[19];
    float* out = (float*)d_out;

    __half *Wcat, *Wocat, *Wp, *hbuf, *hl, *embH, *ftH;
    float *bcat, *bocat, *pb, *c;
    cudaGetSymbolAddress((void**)&Wcat,  g_Wcat);
    cudaGetSymbolAddress((void**)&bcat,  g_bcat);
    cudaGetSymbolAddress((void**)&Wocat, g_Wocat);
    cudaGetSymbolAddress((void**)&bocat, g_bocat);
    cudaGetSymbolAddress((void**)&Wp,    g_Wp);
    cudaGetSymbolAddress((void**)&pb,    g_pb);
    cudaGetSymbolAddress((void**)&hbuf,  g_hbuf);
    cudaGetSymbolAddress((void**)&c,     g_c);
    cudaGetSymbolAddress((void**)&hl,    g_hl);
    cudaGetSymbolAddress((void**)&embH,  g_embH);
    cudaGetSymbolAddress((void**)&ftH,   g_ftH);

    cudaFuncSetAttribute(hgemm<0>, cudaFuncAttributeMaxDynamicSharedMemorySize, SMEM_BYTES);
    cudaFuncSetAttribute(hgemm<1>, cudaFuncAttributeMaxDynamicSharedMemorySize, SMEM_BYTES);

    // prep: weight norm (fp16), permute (fp16), convert activations
    wn_kernel<<<Hc, 256>>>(v_ih0, g_ih0, Wcat,            Ac);
    wn_kernel<<<Hc, 256>>>(v_ic0, g_ic0, Wcat + Hc * Ac,  Ac);
    wn_kernel<<<Lc, 256>>>(v_mu,  g_mu,  Wocat,           Hc);
    wn_kernel<<<Lc, 256>>>(v_s2,  g_s2,  Wocat + Lc * Hc, Hc);
    pack2<<<(2 * Hc + 255) / 256, 256>>>(b_ih0, b_ic0, bcat, Hc);
    pack2<<<(2 * Lc + 255) / 256, 256>>>(b_mu,  b_s2,  bocat, Lc);
    permute_kernel<<<Nw, 256>>>(W_hh, W_ih, b_ih, b_hh, Wp, pb);
    half_copy<<<(Vc * Ec + 255) / 256, 256>>>(embed, embH, Vc * Ec);
    half_copy<<<(Bc * Ac + 255) / 256, 256>>>(feat, ftH, Bc * Ac);

    // init: h0 (fp16) and c0 (fp32), fused N=2048
    {
        dim3 grid(2 * Hc / 128, Bc / 128);   // (16, 8)
        hgemm<0><<<grid, 256, SMEM_BYTES>>>(ftH, Ac, Ac / 32, nullptr, 0, 0, nullptr, 0,
                                            Wcat, Ac, bcat,
                                            (float*)hbuf, Hc, 1, c, Hc, 0, Hc,
                                            nullptr, nullptr, nullptr, nullptr);
    }

    // recurrence: [h | emb(cap_t)] @ Wp^T + pb, fused LSTM cell, double-buffered h
    {
        dim3 grid(Nw / 128, Bc / 128);       // (32, 8) = 256 CTAs, 2/SM
        for (int t = 0; t < Tc; t++) {
            __half* hin  = hbuf + (size_t)(t & 1) * Bc * Hc;
            __half* hout = hbuf + (size_t)((t + 1) & 1) * Bc * Hc;
            hgemm<1><<<grid, 256, SMEM_BYTES>>>(hin, Hc, Hc / 32, embH, Ec, Ec / 32, cap, t,
                                                Wp, Hc + Ec, pb,
                                                nullptr, 0, 0, nullptr, 0, 0, 0,
                                                cap_len, c, hout, hl);
        }
    }

    // outputs: mu and sigma2 fused, N=512, fp32 epilogue
    {
        dim3 grid(2 * Lc / 128, Bc / 128);   // (4, 8)
        hgemm<0><<<grid, 256, SMEM_BYTES>>>(hl, Hc, Hc / 32, nullptr, 0, 0, nullptr, 0,
                                            Wocat, Hc, bocat,
                                            out, Lc, 0, out + Bc * Lc, Lc, 0, Lc,
                                            nullptr, nullptr, nullptr, nullptr);
    }
}

// round 7
// speedup vs baseline: 1.6917x; 1.0320x over previous
#include <cuda_runtime.h>
#include <cuda_fp16.h>
#include <cstdint>
#include <math.h>

// ---------------- problem constants ----------------
#define Bc 1024   // batch
#define Tc 40     // timesteps
#define Ec 512    // embed dim
#define Hc 1024   // hidden
#define Lc 256    // latent out
#define Ac 2048   // feature dim
#define Vc 30000  // vocab
#define Nw 4096   // 4*H
#define NCTA 256  // persistent grid size

// ---------------- device scratch (no allocation) ----------------
__device__ __half g_Wcat [2 * Hc * Ac];   // [Wih0 ; Wic0] weight-normed fp16
__device__ float  g_bcat [2 * Hc];        // [b_ih0 ; b_ic0]
__device__ __half g_Wocat[2 * Lc * Hc];   // [Wmu ; Ws2] weight-normed fp16
__device__ float  g_bocat[2 * Lc];        // [b_mu ; b_s2]
__device__ __half g_Wp   [Nw * (Hc + Ec)];// permuted [4j+gate][W_hh | W_ih] fp16
__device__ float  g_pb   [Nw];            // permuted bias b_ih+b_hh
__device__ __half g_hbuf [2][Bc * Hc];    // double-buffered hidden (fp16)
__device__ float  g_c0   [Bc * Hc];       // initial cell state (fp32)
__device__ __half g_hl   [Bc * Hc];       // h at last valid step (fp16)
__device__ __half g_embH [Vc * Ec];       // fp16 embedding
__device__ __half g_ftH  [Bc * Ac];       // fp16 feat_vec
__device__ unsigned int g_counter;        // global step barrier

// ---------------- helpers ----------------
__device__ __forceinline__ uint32_t smem_u32(const void* p) {
    uint32_t a;
    asm("{ .reg .u64 t; cvta.to.shared.u64 t, %1; cvt.u32.u64 %0, t; }" : "=r"(a) : "l"(p));
    return a;
}
#define CP_ASYNC16(dst, src) \
    asm volatile("cp.async.cg.shared.global [%0], [%1], 16;" :: "r"(dst), "l"(src))
#define CP_COMMIT() asm volatile("cp.async.commit_group;" ::: "memory")
#define CP_WAIT2()  asm volatile("cp.async.wait_group 2;" ::: "memory")

__device__ __forceinline__ void mma_f16(float* d, const uint32_t* a, const uint32_t* b) {
    asm volatile(
        "mma.sync.aligned.m16n8k16.row.col.f32.f16.f16.f32 "
        "{%0,%1,%2,%3}, {%4,%5,%6,%7}, {%8,%9}, {%0,%1,%2,%3};"
        : "+f"(d[0]), "+f"(d[1]), "+f"(d[2]), "+f"(d[3])
        : "r"(a[0]), "r"(a[1]), "r"(a[2]), "r"(a[3]), "r"(b[0]), "r"(b[1]));
}

// ---------------- prep kernels ----------------
__global__ void wn_kernel(const float* __restrict__ v, const float* __restrict__ g,
                          __half* __restrict__ W, int cols) {
    int r = blockIdx.x;
    const float* vr = v + (size_t)r * cols;
    float s = 0.f;
    for (int c = threadIdx.x; c < cols; c += blockDim.x) { float x = vr[c]; s += x * x; }
    __shared__ float sh[32];
    for (int o = 16; o > 0; o >>= 1) s += __shfl_down_sync(0xffffffffu, s, o);
    if ((threadIdx.x & 31) == 0) sh[threadIdx.x >> 5] = s;
    __syncthreads();
    if (threadIdx.x < 32) {
        float t = (threadIdx.x < (blockDim.x >> 5)) ? sh[threadIdx.x] : 0.f;
        for (int o = 16; o > 0; o >>= 1) t += __shfl_down_sync(0xffffffffu, t, o);
        if (threadIdx.x == 0) sh[0] = t;
    }
    __syncthreads();
    float scale = g[r] / sqrtf(sh[0]);
    __half* Wr = W + (size_t)r * cols;
    for (int c = threadIdx.x; c < cols; c += blockDim.x) Wr[c] = __float2half_rn(vr[c] * scale);
}

__global__ void permute_kernel(const float* __restrict__ Whh, const float* __restrict__ Wih,
                               const float* __restrict__ bih, const float* __restrict__ bhh,
                               __half* __restrict__ Wp, float* __restrict__ pb) {
    int n = blockIdx.x;
    int gt = n >> 10, j = n & 1023;
    int np = (j << 2) | gt;
    __half* dst = Wp + (size_t)np * (Hc + Ec);
    const float* s1 = Whh + (size_t)n * Hc;
    const float* s2 = Wih + (size_t)n * Ec;
    for (int k = threadIdx.x; k < Hc; k += blockDim.x) dst[k] = __float2half_rn(s1[k]);
    for (int k = threadIdx.x; k < Ec; k += blockDim.x) dst[Hc + k] = __float2half_rn(s2[k]);
    if (threadIdx.x == 0) pb[np] = bih[n] + bhh[n];
}

__global__ void half_copy(const float* __restrict__ src, __half* __restrict__ dst, int n) {
    int i = blockIdx.x * blockDim.x + threadIdx.x;
    if (i < n) dst[i] = __float2half_rn(src[i]);
}

__global__ void pack2(const float* __restrict__ a, const float* __restrict__ b,
                      float* __restrict__ dst, int n) {
    int i = blockIdx.x * blockDim.x + threadIdx.x;
    if (i < n) dst[i] = a[i];
    else if (i < 2 * n) dst[i] = b[i - n];
}

// ---------------- fp16 mma.sync GEMM (init / output projections) ----------------
static constexpr int ST    = 128 * 80;                    // 10240 B per stage
static constexpr int A_OFF = 1024;
static constexpr int B_OFF = A_OFF + 4 * ST;
static constexpr int SMEM_G = B_OFF + 4 * ST;             // 82944

__global__ __launch_bounds__(256, 2)
void hgemm(const __half* __restrict__ A1, int lda1, int kc1,
           const __half* __restrict__ Bw, int ldb,
           const float* __restrict__ bias,
           float* __restrict__ C1, int ldc1, int half1,
           float* __restrict__ C2, int ldc2, int half2, int ncut)
{
    extern __shared__ __align__(1024) char smem[];
    uint32_t sb = smem_u32(smem);
    int tid = threadIdx.x, wid = tid >> 5, lid = tid & 31;
    int g = lid >> 2, tig = lid & 3;
    int warpM = (wid & 1) * 64, warpN = (wid >> 1) * 32;
    int bm = blockIdx.y * 128, bn = blockIdx.x * 128;
    const int NC = kc1;

    float acc[4][4][4];
#pragma unroll
    for (int i = 0; i < 4; i++)
#pragma unroll
        for (int j = 0; j < 4; j++)
#pragma unroll
            for (int q = 0; q < 4; q++) acc[i][j][q] = 0.f;

    auto load_chunk = [&](int c, int s) {
        uint32_t aB = sb + A_OFF + s * ST;
        uint32_t bB = sb + B_OFF + s * ST;
#pragma unroll
        for (int i = 0; i < 2; i++) {
            int seg = tid + i * 256;
            int m = seg >> 2, sg = seg & 3;
            CP_ASYNC16(aB + m * 80 + sg * 16, A1 + (size_t)(bm + m) * lda1 + c * 32 + sg * 8);
        }
#pragma unroll
        for (int i = 0; i < 2; i++) {
            int seg = tid + i * 256;
            int n = seg >> 2, sg = seg & 3;
            CP_ASYNC16(bB + n * 80 + sg * 16, Bw + (size_t)(bn + n) * ldb + c * 32 + sg * 8);
        }
    };

    for (int p = 0; p < 3; p++) { load_chunk(p, p); CP_COMMIT(); }

    for (int c = 0; c < NC; c++) {
        int s = c & 3;
        CP_WAIT2();
        __syncthreads();
        if (c + 3 < NC) load_chunk(c + 3, (c + 3) & 3);
        CP_COMMIT();
        const uint32_t* aU = (const uint32_t*)(smem + A_OFF + s * ST);
        const uint32_t* bU = (const uint32_t*)(smem + B_OFF + s * ST);
#pragma unroll
        for (int k16 = 0; k16 < 2; k16++) {
            uint32_t afr[4][4], bfr[4][2];
            int kb = k16 * 8 + tig;
#pragma unroll
            for (int rb = 0; rb < 4; rb++) {
                int ar = warpM + rb * 16 + g;
                afr[rb][0] = aU[ar * 20 + kb];
                afr[rb][1] = aU[(ar + 8) * 20 + kb];
                afr[rb][2] = aU[ar * 20 + kb + 4];
                afr[rb][3] = aU[(ar + 8) * 20 + kb + 4];
            }
#pragma unroll
            for (int nb = 0; nb < 4; nb++) {
                int br = warpN + nb * 8 + g;
                bfr[nb][0] = bU[br * 20 + kb];
                bfr[nb][1] = bU[br * 20 + kb + 4];
            }
#pragma unroll
            for (int rb = 0; rb < 4; rb++)
#pragma unroll
                for (int nb = 0; nb < 4; nb++)
                    mma_f16(acc[rb][nb], afr[rb], bfr[nb]);
        }
    }

    float* Cd; int cb, ldc, hf;
    if (bn < ncut) { Cd = C1; cb = bn;        ldc = ldc1; hf = half1; }
    else           { Cd = C2; cb = bn - ncut; ldc = ldc2; hf = half2; }
#pragma unroll
    for (int rb = 0; rb < 4; rb++) {
#pragma unroll
        for (int nb = 0; nb < 4; nb++) {
            int coll = warpN + nb * 8 + 2 * tig;
            int col = cb + coll;
            int r0 = bm + warpM + rb * 16 + g;
            float b0 = bias[bn + coll], b1 = bias[bn + coll + 1];
            float v0 = acc[rb][nb][0] + b0, v1 = acc[rb][nb][1] + b1;
            float v2 = acc[rb][nb][2] + b0, v3 = acc[rb][nb][3] + b1;
            if (hf) {
                __half* Ch = (__half*)Cd;
                *(__half2*)(Ch + (size_t)r0 * ldc + col)       = __floats2half2_rn(v0, v1);
                *(__half2*)(Ch + (size_t)(r0 + 8) * ldc + col) = __floats2half2_rn(v2, v3);
            } else {
                *(float2*)(Cd + (size_t)r0 * ldc + col)       = make_float2(v0, v1);
                *(float2*)(Cd + (size_t)(r0 + 8) * ldc + col) = make_float2(v2, v3);
            }
        }
    }
}

// ---------------- persistent LSTM recurrence ----------------
// 256 CTAs (2/SM, all resident). Each CTA owns (bm, bn): 128 batch x 128 gate cols.
// Per step: 16 embed chunks (no dep) -> barrier (hidden under embed MMA) -> 32 h chunks
// -> fused cell epilogue. c lives in CTA smem for all 40 steps.
static constexpr int CS_OFF = A_OFF + 8 * ST;             // 82944: c state (16 KB)
static constexpr int SMEM_P = CS_OFF + 128 * 32 * 4;      // 99328
static constexpr int GSTR   = 132;

__global__ __launch_bounds__(256, 2)
void lstm_persist(const __half* __restrict__ embH,
                  const int* __restrict__ cap,
                  const __half* __restrict__ Wp,
                  const float* __restrict__ pb,
                  const float* __restrict__ c0,
                  __half* __restrict__ hbuf,
                  __half* __restrict__ hlast,
                  const int* __restrict__ cap_len,
                  unsigned int* __restrict__ counter)
{
    extern __shared__ __align__(1024) char smem[];
    uint32_t sb = smem_u32(smem);
    int tid = threadIdx.x, wid = tid >> 5, lid = tid & 31;
    int g = lid >> 2, tig = lid & 3;
    int warpM = (wid & 1) * 64, warpN = (wid >> 1) * 32;
    int bn = blockIdx.x * 128, bm = blockIdx.y * 128;
    int jg0 = bn >> 2;
    int* stok = (int*)smem;           // [128] tokens
    int* cl_s = (int*)(smem + 512);   // [128] cap_len
    float* c_s = (float*)(smem + CS_OFF);

    // init CTA-resident state
    for (int idx = tid; idx < 128 * 32; idx += 256) {
        int row = idx >> 5, jl = idx & 31;
        c_s[idx] = c0[(size_t)(bm + row) * Hc + jg0 + jl];
    }
    if (tid < 128) cl_s[tid] = cap_len[bm + tid];

    auto load_chunk = [&](const __half* hin, int c, int s) {
        uint32_t aB = sb + A_OFF + s * ST;
        uint32_t bB = sb + A_OFF + 4 * ST + s * ST;
#pragma unroll
        for (int i = 0; i < 2; i++) {
            int seg = tid + i * 256;
            int m = seg >> 2, sg = seg & 3;
            const __half* src = (c < 16)
                ? embH + (size_t)stok[m] * Ec + c * 32 + sg * 8
                : hin + (size_t)(bm + m) * Hc + (c - 16) * 32 + sg * 8;
            CP_ASYNC16(aB + m * 80 + sg * 16, src);
        }
#pragma unroll
        for (int i = 0; i < 2; i++) {
            int seg = tid + i * 256;
            int n = seg >> 2, sg = seg & 3;
            int kk = (c < 16) ? (Hc + c * 32) : ((c - 16) * 32);
            CP_ASYNC16(bB + n * 80 + sg * 16,
                       Wp + (size_t)(bn + n) * (Hc + Ec) + kk + sg * 8);
        }
    };

    for (int t = 0; t < Tc; t++) {
        __syncthreads();
        if (tid < 128) stok[tid] = cap[(size_t)(bm + tid) * Tc + t];
        __syncthreads();
        const __half* hin  = hbuf + (size_t)(t & 1) * (Bc * Hc);
        __half*       hout = hbuf + (size_t)((t + 1) & 1) * (Bc * Hc);

        float acc[4][4][4];
#pragma unroll
        for (int i = 0; i < 4; i++)
#pragma unroll
            for (int j = 0; j < 4; j++)
#pragma unroll
                for (int q = 0; q < 4; q++) acc[i][j][q] = 0.f;

        // prologue: 3 embed chunks (dependency-free)
        for (int p = 0; p < 3; p++) { load_chunk(hin, p, p); CP_COMMIT(); }

        for (int c = 0; c < 48; c++) {
            if (c == 13) {  // about to issue loads for chunk 16 = first h chunk
                if (tid == 0) {
                    unsigned int target = (unsigned int)(NCTA * t);
                    while (atomicAdd(counter, 0u) < target) {}
                }
                __syncthreads();
            }
            int s = c & 3;
            CP_WAIT2();
            __syncthreads();
            if (c + 3 < 48) load_chunk(hin, c + 3, (c + 3) & 3);
            CP_COMMIT();
            const uint32_t* aU = (const uint32_t*)(smem + A_OFF + s * ST);
            const uint32_t* bU = (const uint32_t*)(smem + A_OFF + 4 * ST + s * ST);
#pragma unroll
            for (int k16 = 0; k16 < 2; k16++) {
                uint32_t afr[4][4], bfr[4][2];
                int kb = k16 * 8 + tig;
#pragma unroll
                for (int rb = 0; rb < 4; rb++) {
                    int ar = warpM + rb * 16 + g;
                    afr[rb][0] = aU[ar * 20 + kb];
                    afr[rb][1] = aU[(ar + 8) * 20 + kb];
                    afr[rb][2] = aU[ar * 20 + kb + 4];
                    afr[rb][3] = aU[(ar + 8) * 20 + kb + 4];
                }
#pragma unroll
                for (int nb = 0; nb < 4; nb++) {
                    int br = warpN + nb * 8 + g;
                    bfr[nb][0] = bU[br * 20 + kb];
                    bfr[nb][1] = bU[br * 20 + kb + 4];
                }
#pragma unroll
                for (int rb = 0; rb < 4; rb++)
#pragma unroll
                    for (int nb = 0; nb < 4; nb++)
                        mma_f16(acc[rb][nb], afr[rb], bfr[nb]);
            }
        }

        // epilogue: stage gates, fused LSTM cell (c in smem)
        __syncthreads();
        float* gsm = (float*)(smem + A_OFF);
#pragma unroll
        for (int rb = 0; rb < 4; rb++) {
#pragma unroll
            for (int nb = 0; nb < 4; nb++) {
                int col = warpN + nb * 8 + 2 * tig;
                int r0 = warpM + rb * 16 + g;
                *(float2*)(gsm + r0 * GSTR + col)       = make_float2(acc[rb][nb][0], acc[rb][nb][1]);
                *(float2*)(gsm + (r0 + 8) * GSTR + col) = make_float2(acc[rb][nb][2], acc[rb][nb][3]);
            }
        }
        __syncthreads();
        for (int idx = tid; idx < 128 * 32; idx += 256) {
            int row = idx >> 5, jl = idx & 31;
            int gm = bm + row;
            float4 gv = *(const float4*)(gsm + row * GSTR + jl * 4);
            int nb4 = bn + jl * 4;
            float gi = gv.x + pb[nb4 + 0];
            float gf = gv.y + pb[nb4 + 1];
            float gg = gv.z + pb[nb4 + 2];
            float go = gv.w + pb[nb4 + 3];
            float si = 1.f / (1.f + expf(-gi));
            float sf = 1.f / (1.f + expf(-gf));
            float so = 1.f / (1.f + expf(-go));
            float cn = sf * c_s[idx] + si * tanhf(gg);
            __half hn = __float2half_rn(so * tanhf(cn));
            c_s[idx] = cn;
            size_t off = (size_t)gm * Hc + jg0 + jl;
            hout[off] = hn;
            if (cl_s[row] - 1 == t) hlast[off] = hn;
        }
        __threadfence();
        __syncthreads();
        if (tid == 0) atomicAdd(counter, 1u);
    }
}

// ---------------- launch ----------------
extern "C" void kernel_launch(void* const* d_in, const int* in_sizes, int n_in,
                              void* d_out, int out_size) {
    const int*   cap     = (const int*)  d_in[0];
    const int*   cap_len = (const int*)  d_in[1];
    const float* feat    = (const float*)d_in[2];
    const float* embed   = (const float*)d_in[3];
    const float* W_ih    = (const float*)d_in[4];
    const float* W_hh    = (const float*)d_in[5];
    const float* b_ih    = (const float*)d_in[6];
    const float* b_hh    = (const float*)d_in[7];
    const float* v_ih0   = (const float*)d_in[8];
    const float* g_ih0   = (const float*)d_in[9];
    const float* b_ih0   = (const float*)d_in[10];
    const float* v_ic0   = (const float*)d_in[11];
    const float* g_ic0   = (const float*)d_in[12];
    const float* b_ic0   = (const float*)d_in[13];
    const float* v_mu    = (const float*)d_in[14];
    const float* g_mu    = (const float*)d_in[15];
    const float* b_mu    = (const float*)d_in[16];
    const float* v_s2    = (const float*)d_in[17];
    const float* g_s2    = (const float*)d_in[18];
    const float* b_s2    = (const float*)d_in[19];
    float* out = (float*)d_out;

    __half *Wcat, *Wocat, *Wp, *hbuf, *hl, *embH, *ftH;
    float *bcat, *bocat, *pb, *c0;
    unsigned int* counter;
    cudaGetSymbolAddress((void**)&Wcat,    g_Wcat);
    cudaGetSymbolAddress((void**)&bcat,    g_bcat);
    cudaGetSymbolAddress((void**)&Wocat,   g_Wocat);
    cudaGetSymbolAddress((void**)&bocat,   g_bocat);
    cudaGetSymbolAddress((void**)&Wp,      g_Wp);
    cudaGetSymbolAddress((void**)&pb,      g_pb);
    cudaGetSymbolAddress((void**)&hbuf,    g_hbuf);
    cudaGetSymbolAddress((void**)&c0,      g_c0);
    cudaGetSymbolAddress((void**)&hl,      g_hl);
    cudaGetSymbolAddress((void**)&embH,    g_embH);
    cudaGetSymbolAddress((void**)&ftH,     g_ftH);
    cudaGetSymbolAddress((void**)&counter, g_counter);

    cudaFuncSetAttribute(hgemm,        cudaFuncAttributeMaxDynamicSharedMemorySize, SMEM_G);
    cudaFuncSetAttribute(lstm_persist, cudaFuncAttributeMaxDynamicSharedMemorySize, SMEM_P);

    cudaMemsetAsync(counter, 0, sizeof(unsigned int));

    // prep: weight norm (fp16), permute (fp16), convert activations
    wn_kernel<<<Hc, 256>>>(v_ih0, g_ih0, Wcat,            Ac);
    wn_kernel<<<Hc, 256>>>(v_ic0, g_ic0, Wcat + Hc * Ac,  Ac);
    wn_kernel<<<Lc, 256>>>(v_mu,  g_mu,  Wocat,           Hc);
    wn_kernel<<<Lc, 256>>>(v_s2,  g_s2,  Wocat + Lc * Hc, Hc);
    pack2<<<(2 * Hc + 255) / 256, 256>>>(b_ih0, b_ic0, bcat, Hc);
    pack2<<<(2 * Lc + 255) / 256, 256>>>(b_mu,  b_s2,  bocat, Lc);
    permute_kernel<<<Nw, 256>>>(W_hh, W_ih, b_ih, b_hh, Wp, pb);
    half_copy<<<(Vc * Ec + 255) / 256, 256>>>(embed, embH, Vc * Ec);
    half_copy<<<(Bc * Ac + 255) / 256, 256>>>(feat, ftH, Bc * Ac);

    // init: h0 (fp16, into hbuf[0]) and c0 (fp32), fused N=2048
    {
        dim3 grid(2 * Hc / 128, Bc / 128);   // (16, 8)
        hgemm<<<grid, 256, SMEM_G>>>(ftH, Ac, Ac / 32, Wcat, Ac, bcat,
                                     (float*)hbuf, Hc, 1, c0, Hc, 0, Hc);
    }

    // recurrence: ONE persistent kernel, 40 steps, global spin barrier
    {
        dim3 grid(Nw / 128, Bc / 128);       // (32, 8) = 256 CTAs, 2/SM all resident
        lstm_persist<<<grid, 256, SMEM_P>>>(embH, cap, Wp, pb, c0, hbuf, hl, cap_len, counter);
    }

    // outputs: mu and sigma2 fused, N=512, fp32 epilogue
    {
        dim3 grid(2 * Lc / 128, Bc / 128);   // (4, 8)
        hgemm<<<grid, 256, SMEM_G>>>(hl, Hc, Hc / 32, Wocat, Hc, bocat,
                                     out, Lc, 0, out + Bc * Lc, Lc, 0, Lc);
    }
}

// round 8
// speedup vs baseline: 2.2028x; 1.3021x over previous
#include <cuda_runtime.h>
#include <cuda_fp16.h>
#include <cstdint>
#include <math.h>

// ---------------- problem constants ----------------
#define Bc 1024   // batch
#define Tc 40     // timesteps
#define Ec 512    // embed dim
#define Hc 1024   // hidden
#define Lc 256    // latent out
#define Ac 2048   // feature dim
#define Vc 30000  // vocab
#define Nw 4096   // 4*H
#define NCTA 256  // persistent grid size

// ---------------- device scratch (no allocation) ----------------
__device__ __half g_Wcat [2 * Hc * Ac];   // [Wih0 ; Wic0] weight-normed fp16
__device__ float  g_bcat [2 * Hc];        // [b_ih0 ; b_ic0]
__device__ __half g_Wocat[2 * Lc * Hc];   // [Wmu ; Ws2] weight-normed fp16
__device__ float  g_bocat[2 * Lc];        // [b_mu ; b_s2]
__device__ __half g_Wp   [Nw * (Hc + Ec)];// permuted [4j+gate][W_hh | W_ih] fp16
__device__ float  g_pb   [Nw];            // permuted bias b_ih+b_hh
__device__ __half g_hbuf [2][Bc * Hc];    // double-buffered hidden (fp16)
__device__ float  g_c0   [Bc * Hc];       // initial cell state (fp32)
__device__ __half g_hl   [Bc * Hc];       // h at last valid step (fp16)
__device__ __half g_embH [Vc * Ec];       // fp16 embedding
__device__ __half g_ftH  [Bc * Ac];       // fp16 feat_vec
__device__ unsigned int g_counter;        // global step barrier

// ---------------- helpers ----------------
__device__ __forceinline__ uint32_t smem_u32(const void* p) {
    uint32_t a;
    asm("{ .reg .u64 t; cvta.to.shared.u64 t, %1; cvt.u32.u64 %0, t; }" : "=r"(a) : "l"(p));
    return a;
}
#define CP_ASYNC16(dst, src) \
    asm volatile("cp.async.cg.shared.global [%0], [%1], 16;" :: "r"(dst), "l"(src))
#define CP_COMMIT() asm volatile("cp.async.commit_group;" ::: "memory")
#define CP_WAIT2()  asm volatile("cp.async.wait_group 2;" ::: "memory")

__device__ __forceinline__ void mma_f16(float* d, const uint32_t* a, const uint32_t* b) {
    asm volatile(
        "mma.sync.aligned.m16n8k16.row.col.f32.f16.f16.f32 "
        "{%0,%1,%2,%3}, {%4,%5,%6,%7}, {%8,%9}, {%0,%1,%2,%3};"
        : "+f"(d[0]), "+f"(d[1]), "+f"(d[2]), "+f"(d[3])
        : "r"(a[0]), "r"(a[1]), "r"(a[2]), "r"(a[3]), "r"(b[0]), "r"(b[1]));
}
__device__ __forceinline__ void ldsm_x4(uint32_t* r, uint32_t addr) {
    asm volatile("ldmatrix.sync.aligned.m8n8.x4.shared.b16 {%0,%1,%2,%3}, [%4];"
        : "=r"(r[0]), "=r"(r[1]), "=r"(r[2]), "=r"(r[3]) : "r"(addr));
}
// fast activations: ex2.approx + rcp.approx (error ~1e-7, way below fp16 noise)
__device__ __forceinline__ float fex2(float x) { float r; asm("ex2.approx.f32 %0, %1;" : "=f"(r) : "f"(x)); return r; }
__device__ __forceinline__ float frcp(float x) { float r; asm("rcp.approx.f32 %0, %1;" : "=f"(r) : "f"(x)); return r; }
__device__ __forceinline__ float fsig(float x)  { return frcp(1.f + fex2(-1.4426950408889634f * x)); }
__device__ __forceinline__ float ftanh(float x) { return 1.f - 2.f * frcp(1.f + fex2(2.8853900817779268f * x)); }

// ---------------- prep kernels ----------------
__global__ void wn_kernel(const float* __restrict__ v, const float* __restrict__ g,
                          __half* __restrict__ W, int cols) {
    int r = blockIdx.x;
    const float* vr = v + (size_t)r * cols;
    float s = 0.f;
    for (int c = threadIdx.x; c < cols; c += blockDim.x) { float x = vr[c]; s += x * x; }
    __shared__ float sh[32];
    for (int o = 16; o > 0; o >>= 1) s += __shfl_down_sync(0xffffffffu, s, o);
    if ((threadIdx.x & 31) == 0) sh[threadIdx.x >> 5] = s;
    __syncthreads();
    if (threadIdx.x < 32) {
        float t = (threadIdx.x < (blockDim.x >> 5)) ? sh[threadIdx.x] : 0.f;
        for (int o = 16; o > 0; o >>= 1) t += __shfl_down_sync(0xffffffffu, t, o);
        if (threadIdx.x == 0) sh[0] = t;
    }
    __syncthreads();
    float scale = g[r] / sqrtf(sh[0]);
    __half* Wr = W + (size_t)r * cols;
    for (int c = threadIdx.x; c < cols; c += blockDim.x) Wr[c] = __float2half_rn(vr[c] * scale);
}

__global__ void permute_kernel(const float* __restrict__ Whh, const float* __restrict__ Wih,
                               const float* __restrict__ bih, const float* __restrict__ bhh,
                               __half* __restrict__ Wp, float* __restrict__ pb) {
    int n = blockIdx.x;
    int gt = n >> 10, j = n & 1023;
    int np = (j << 2) | gt;
    __half* dst = Wp + (size_t)np * (Hc + Ec);
    const float* s1 = Whh + (size_t)n * Hc;
    const float* s2 = Wih + (size_t)n * Ec;
    for (int k = threadIdx.x; k < Hc; k += blockDim.x) dst[k] = __float2half_rn(s1[k]);
    for (int k = threadIdx.x; k < Ec; k += blockDim.x) dst[Hc + k] = __float2half_rn(s2[k]);
    if (threadIdx.x == 0) pb[np] = bih[n] + bhh[n];
}

__global__ void half_copy(const float* __restrict__ src, __half* __restrict__ dst, int n) {
    int i = blockIdx.x * blockDim.x + threadIdx.x;
    if (i < n) dst[i] = __float2half_rn(src[i]);
}

__global__ void pack2(const float* __restrict__ a, const float* __restrict__ b,
                      float* __restrict__ dst, int n) {
    int i = blockIdx.x * blockDim.x + threadIdx.x;
    if (i < n) dst[i] = a[i];
    else if (i < 2 * n) dst[i] = b[i - n];
}

// ---------------- fp16 mma.sync GEMM (init / output projections) ----------------
static constexpr int ST    = 128 * 80;                    // 10240 B per stage
static constexpr int A_OFF = 1024;
static constexpr int B_OFF = A_OFF + 4 * ST;
static constexpr int SMEM_G = B_OFF + 4 * ST;             // 82944

__global__ __launch_bounds__(256, 2)
void hgemm(const __half* __restrict__ A1, int lda1, int kc1,
           const __half* __restrict__ Bw, int ldb,
           const float* __restrict__ bias,
           float* __restrict__ C1, int ldc1, int half1,
           float* __restrict__ C2, int ldc2, int half2, int ncut)
{
    extern __shared__ __align__(1024) char smem[];
    uint32_t sb = smem_u32(smem);
    int tid = threadIdx.x, wid = tid >> 5, lid = tid & 31;
    int g = lid >> 2, tig = lid & 3;
    int warpM = (wid & 1) * 64, warpN = (wid >> 1) * 32;
    int bm = blockIdx.y * 128, bn = blockIdx.x * 128;
    const int NC = kc1;

    // ldmatrix per-lane offsets
    uint32_t offA[4], offB[2];
#pragma unroll
    for (int rb = 0; rb < 4; rb++)
        offA[rb] = (warpM + rb * 16 + (lid & 15)) * 80 + (lid >> 4) * 16;
#pragma unroll
    for (int p = 0; p < 2; p++)
        offB[p] = (warpN + p * 16 + ((lid >> 4) << 3) + (lid & 7)) * 80 + ((lid >> 3) & 1) * 16;

    float acc[4][4][4];
#pragma unroll
    for (int i = 0; i < 4; i++)
#pragma unroll
        for (int j = 0; j < 4; j++)
#pragma unroll
            for (int q = 0; q < 4; q++) acc[i][j][q] = 0.f;

    auto load_chunk = [&](int c, int s) {
        uint32_t aB = sb + A_OFF + s * ST;
        uint32_t bB = sb + B_OFF + s * ST;
#pragma unroll
        for (int i = 0; i < 2; i++) {
            int seg = tid + i * 256;
            int m = seg >> 2, sg = seg & 3;
            CP_ASYNC16(aB + m * 80 + sg * 16, A1 + (size_t)(bm + m) * lda1 + c * 32 + sg * 8);
        }
#pragma unroll
        for (int i = 0; i < 2; i++) {
            int seg = tid + i * 256;
            int n = seg >> 2, sg = seg & 3;
            CP_ASYNC16(bB + n * 80 + sg * 16, Bw + (size_t)(bn + n) * ldb + c * 32 + sg * 8);
        }
    };

    for (int p = 0; p < 3; p++) { load_chunk(p, p); CP_COMMIT(); }

    for (int c = 0; c < NC; c++) {
        int s = c & 3;
        CP_WAIT2();
        __syncthreads();
        if (c + 3 < NC) load_chunk(c + 3, (c + 3) & 3);
        CP_COMMIT();
        uint32_t aB = sb + A_OFF + s * ST;
        uint32_t bB = sb + B_OFF + s * ST;
#pragma unroll
        for (int k16 = 0; k16 < 2; k16++) {
            uint32_t afr[4][4], bfr[2][4];
#pragma unroll
            for (int rb = 0; rb < 4; rb++) ldsm_x4(afr[rb], aB + offA[rb] + k16 * 32);
#pragma unroll
            for (int p = 0; p < 2; p++) ldsm_x4(bfr[p], bB + offB[p] + k16 * 32);
#pragma unroll
            for (int rb = 0; rb < 4; rb++) {
                mma_f16(acc[rb][0], afr[rb], &bfr[0][0]);
                mma_f16(acc[rb][1], afr[rb], &bfr[0][2]);
                mma_f16(acc[rb][2], afr[rb], &bfr[1][0]);
                mma_f16(acc[rb][3], afr[rb], &bfr[1][2]);
            }
        }
    }

    float* Cd; int cb, ldc, hf;
    if (bn < ncut) { Cd = C1; cb = bn;        ldc = ldc1; hf = half1; }
    else           { Cd = C2; cb = bn - ncut; ldc = ldc2; hf = half2; }
#pragma unroll
    for (int rb = 0; rb < 4; rb++) {
#pragma unroll
        for (int nb = 0; nb < 4; nb++) {
            int coll = warpN + nb * 8 + 2 * tig;
            int col = cb + coll;
            int r0 = bm + warpM + rb * 16 + g;
            float b0 = bias[bn + coll], b1 = bias[bn + coll + 1];
            float v0 = acc[rb][nb][0] + b0, v1 = acc[rb][nb][1] + b1;
            float v2 = acc[rb][nb][2] + b0, v3 = acc[rb][nb][3] + b1;
            if (hf) {
                __half* Ch = (__half*)Cd;
                *(__half2*)(Ch + (size_t)r0 * ldc + col)       = __floats2half2_rn(v0, v1);
                *(__half2*)(Ch + (size_t)(r0 + 8) * ldc + col) = __floats2half2_rn(v2, v3);
            } else {
                *(float2*)(Cd + (size_t)r0 * ldc + col)       = make_float2(v0, v1);
                *(float2*)(Cd + (size_t)(r0 + 8) * ldc + col) = make_float2(v2, v3);
            }
        }
    }
}

// ---------------- persistent LSTM recurrence ----------------
static constexpr int CS_OFF = A_OFF + 8 * ST;             // 82944: c state (16 KB)
static constexpr int SMEM_P = CS_OFF + 128 * 32 * 4;      // 99328
static constexpr int GSTR   = 132;

__global__ __launch_bounds__(256, 2)
void lstm_persist(const __half* __restrict__ embH,
                  const int* __restrict__ cap,
                  const __half* __restrict__ Wp,
                  const float* __restrict__ pb,
                  const float* __restrict__ c0,
                  __half* __restrict__ hbuf,
                  __half* __restrict__ hlast,
                  const int* __restrict__ cap_len,
                  unsigned int* __restrict__ counter)
{
    extern __shared__ __align__(1024) char smem[];
    uint32_t sb = smem_u32(smem);
    int tid = threadIdx.x, wid = tid >> 5, lid = tid & 31;
    int g = lid >> 2, tig = lid & 3;
    int warpM = (wid & 1) * 64, warpN = (wid >> 1) * 32;
    int bn = blockIdx.x * 128, bm = blockIdx.y * 128;
    int jg0 = bn >> 2;
    int* stok = (int*)smem;           // [128] tokens
    int* cl_s = (int*)(smem + 512);   // [128] cap_len
    float* c_s = (float*)(smem + CS_OFF);

    uint32_t offA[4], offB[2];
#pragma unroll
    for (int rb = 0; rb < 4; rb++)
        offA[rb] = (warpM + rb * 16 + (lid & 15)) * 80 + (lid >> 4) * 16;
#pragma unroll
    for (int p = 0; p < 2; p++)
        offB[p] = (warpN + p * 16 + ((lid >> 4) << 3) + (lid & 7)) * 80 + ((lid >> 3) & 1) * 16;

    for (int idx = tid; idx < 128 * 32; idx += 256) {
        int row = idx >> 5, jl = idx & 31;
        c_s[idx] = c0[(size_t)(bm + row) * Hc + jg0 + jl];
    }
    if (tid < 128) cl_s[tid] = cap_len[bm + tid];

    auto load_chunk = [&](const __half* hin, int c, int s) {
        uint32_t aB = sb + A_OFF + s * ST;
        uint32_t bB = sb + A_OFF + 4 * ST + s * ST;
#pragma unroll
        for (int i = 0; i < 2; i++) {
            int seg = tid + i * 256;
            int m = seg >> 2, sg = seg & 3;
            const __half* src = (c < 16)
                ? embH + (size_t)stok[m] * Ec + c * 32 + sg * 8
                : hin + (size_t)(bm + m) * Hc + (c - 16) * 32 + sg * 8;
            CP_ASYNC16(aB + m * 80 + sg * 16, src);
        }
#pragma unroll
        for (int i = 0; i < 2; i++) {
            int seg = tid + i * 256;
            int n = seg >> 2, sg = seg & 3;
            int kk = (c < 16) ? (Hc + c * 32) : ((c - 16) * 32);
            CP_ASYNC16(bB + n * 80 + sg * 16,
                       Wp + (size_t)(bn + n) * (Hc + Ec) + kk + sg * 8);
        }
    };

    for (int t = 0; t < Tc; t++) {
        __syncthreads();
        if (tid < 128) stok[tid] = cap[(size_t)(bm + tid) * Tc + t];
        __syncthreads();
        const __half* hin  = hbuf + (size_t)(t & 1) * (Bc * Hc);
        __half*       hout = hbuf + (size_t)((t + 1) & 1) * (Bc * Hc);

        float acc[4][4][4];
#pragma unroll
        for (int i = 0; i < 4; i++)
#pragma unroll
            for (int j = 0; j < 4; j++)
#pragma unroll
                for (int q = 0; q < 4; q++) acc[i][j][q] = 0.f;

        // prologue: 3 embed chunks (dependency-free)
        for (int p = 0; p < 3; p++) { load_chunk(hin, p, p); CP_COMMIT(); }

        for (int c = 0; c < 48; c++) {
            if (c == 13) {  // barrier before first h-chunk load (chunk 16)
                if (tid == 0) {
                    unsigned int target = (unsigned int)(NCTA * t);
                    unsigned int v;
                    do {
                        asm volatile("ld.acquire.gpu.global.u32 %0, [%1];"
                                     : "=r"(v) : "l"(counter) : "memory");
                    } while (v < target);
                }
                __syncthreads();
            }
            int s = c & 3;
            CP_WAIT2();
            __syncthreads();
            if (c + 3 < 48) load_chunk(hin, c + 3, (c + 3) & 3);
            CP_COMMIT();
            uint32_t aB = sb + A_OFF + s * ST;
            uint32_t bB = sb + A_OFF + 4 * ST + s * ST;
#pragma unroll
            for (int k16 = 0; k16 < 2; k16++) {
                uint32_t afr[4][4], bfr[2][4];
#pragma unroll
                for (int rb = 0; rb < 4; rb++) ldsm_x4(afr[rb], aB + offA[rb] + k16 * 32);
#pragma unroll
                for (int p = 0; p < 2; p++) ldsm_x4(bfr[p], bB + offB[p] + k16 * 32);
#pragma unroll
                for (int rb = 0; rb < 4; rb++) {
                    mma_f16(acc[rb][0], afr[rb], &bfr[0][0]);
                    mma_f16(acc[rb][1], afr[rb], &bfr[0][2]);
                    mma_f16(acc[rb][2], afr[rb], &bfr[1][0]);
                    mma_f16(acc[rb][3], afr[rb], &bfr[1][2]);
                }
            }
        }

        // epilogue: stage gates, fused LSTM cell (c in smem), fast activations
        __syncthreads();
        float* gsm = (float*)(smem + A_OFF);
#pragma unroll
        for (int rb = 0; rb < 4; rb++) {
#pragma unroll
            for (int nb = 0; nb < 4; nb++) {
                int col = warpN + nb * 8 + 2 * tig;
                int r0 = warpM + rb * 16 + g;
                *(float2*)(gsm + r0 * GSTR + col)       = make_float2(acc[rb][nb][0], acc[rb][nb][1]);
                *(float2*)(gsm + (r0 + 8) * GSTR + col) = make_float2(acc[rb][nb][2], acc[rb][nb][3]);
            }
        }
        __syncthreads();
        for (int idx = tid; idx < 128 * 32; idx += 256) {
            int row = idx >> 5, jl = idx & 31;
            int gm = bm + row;
            float4 gv = *(const float4*)(gsm + row * GSTR + jl * 4);
            int nb4 = bn + jl * 4;
            float si = fsig(gv.x + pb[nb4 + 0]);
            float sf = fsig(gv.y + pb[nb4 + 1]);
            float tg = ftanh(gv.z + pb[nb4 + 2]);
            float so = fsig(gv.w + pb[nb4 + 3]);
            float cn = sf * c_s[idx] + si * tg;
            __half hn = __float2half_rn(so * ftanh(cn));
            c_s[idx] = cn;
            size_t off = (size_t)gm * Hc + jg0 + jl;
            hout[off] = hn;
            if (cl_s[row] - 1 == t) hlast[off] = hn;
        }
        __syncthreads();
        if (tid == 0)
            asm volatile("red.release.gpu.global.add.u32 [%0], %1;"
                         :: "l"(counter), "r"(1u) : "memory");
    }
}

// ---------------- launch ----------------
extern "C" void kernel_launch(void* const* d_in, const int* in_sizes, int n_in,
                              void* d_out, int out_size) {
    const int*   cap     = (const int*)  d_in[0];
    const int*   cap_len = (const int*)  d_in[1];
    const float* feat    = (const float*)d_in[2];
    const float* embed   = (const float*)d_in[3];
    const float* W_ih    = (const float*)d_in[4];
    const float* W_hh    = (const float*)d_in[5];
    const float* b_ih    = (const float*)d_in[6];
    const float* b_hh    = (const float*)d_in[7];
    const float* v_ih0   = (const float*)d_in[8];
    const float* g_ih0   = (const float*)d_in[9];
    const float* b_ih0   = (const float*)d_in[10];
    const float* v_ic0   = (const float*)d_in[11];
    const float* g_ic0   = (const float*)d_in[12];
    const float* b_ic0   = (const float*)d_in[13];
    const float* v_mu    = (const float*)d_in[14];
    const float* g_mu    = (const float*)d_in[15];
    const float* b_mu    = (const float*)d_in[16];
    const float* v_s2    = (const float*)d_in[17];
    const float* g_s2    = (const float*)d_in[18];
    const float* b_s2    = (const float*)d_in[19];
    float* out = (float*)d_out;

    __half *Wcat, *Wocat, *Wp, *hbuf, *hl, *embH, *ftH;
    float *bcat, *bocat, *pb, *c0;
    unsigned int* counter;
    cudaGetSymbolAddress((void**)&Wcat,    g_Wcat);
    cudaGetSymbolAddress((void**)&bcat,    g_bcat);
    cudaGetSymbolAddress((void**)&Wocat,   g_Wocat);
    cudaGetSymbolAddress((void**)&bocat,   g_bocat);
    cudaGetSymbolAddress((void**)&Wp,      g_Wp);
    cudaGetSymbolAddress((void**)&pb,      g_pb);
    cudaGetSymbolAddress((void**)&hbuf,    g_hbuf);
    cudaGetSymbolAddress((void**)&c0,      g_c0);
    cudaGetSymbolAddress((void**)&hl,      g_hl);
    cudaGetSymbolAddress((void**)&embH,    g_embH);
    cudaGetSymbolAddress((void**)&ftH,     g_ftH);
    cudaGetSymbolAddress((void**)&counter, g_counter);

    cudaFuncSetAttribute(hgemm,        cudaFuncAttributeMaxDynamicSharedMemorySize, SMEM_G);
    cudaFuncSetAttribute(lstm_persist, cudaFuncAttributeMaxDynamicSharedMemorySize, SMEM_P);

    cudaMemsetAsync(counter, 0, sizeof(unsigned int));

    // prep: weight norm (fp16), permute (fp16), convert activations
    wn_kernel<<<Hc, 256>>>(v_ih0, g_ih0, Wcat,            Ac);
    wn_kernel<<<Hc, 256>>>(v_ic0, g_ic0, Wcat + Hc * Ac,  Ac);
    wn_kernel<<<Lc, 256>>>(v_mu,  g_mu,  Wocat,           Hc);
    wn_kernel<<<Lc, 256>>>(v_s2,  g_s2,  Wocat + Lc * Hc, Hc);
    pack2<<<(2 * Hc + 255) / 256, 256>>>(b_ih0, b_ic0, bcat, Hc);
    pack2<<<(2 * Lc + 255) / 256, 256>>>(b_mu,  b_s2,  bocat, Lc);
    permute_kernel<<<Nw, 256>>>(W_hh, W_ih, b_ih, b_hh, Wp, pb);
    half_copy<<<(Vc * Ec + 255) / 256, 256>>>(embed, embH, Vc * Ec);
    half_copy<<<(Bc * Ac + 255) / 256, 256>>>(feat, ftH, Bc * Ac);

    // init: h0 (fp16, into hbuf[0]) and c0 (fp32), fused N=2048
    {
        dim3 grid(2 * Hc / 128, Bc / 128);   // (16, 8)
        hgemm<<<grid, 256, SMEM_G>>>(ftH, Ac, Ac / 32, Wcat, Ac, bcat,
                                     (float*)hbuf, Hc, 1, c0, Hc, 0, Hc);
    }

    // recurrence: ONE persistent kernel, 40 steps, release/acquire step barrier
    {
        dim3 grid(Nw / 128, Bc / 128);       // (32, 8) = 256 CTAs, 2/SM all resident
        lstm_persist<<<grid, 256, SMEM_P>>>(embH, cap, Wp, pb, c0, hbuf, hl, cap_len, counter);
    }

    // outputs: mu and sigma2 fused, N=512, fp32 epilogue
    {
        dim3 grid(2 * Lc / 128, Bc / 128);   // (4, 8)
        hgemm<<<grid, 256, SMEM_G>>>(hl, Hc, Hc / 32, Wocat, Hc, bocat,
                                     out, Lc, 0, out + Bc * Lc, Lc, 0, Lc);
    }
}